// round 2
// baseline (speedup 1.0000x reference)
#include <cuda_runtime.h>
#include <math.h>
#include <stdint.h>

#define NCONF 8192
#define NT 64
#define NX 64

// ---------------------------------------------------------------------------
// Single fused kernel.
// Blocks 0..8191 (64 threads): per-config  T0 -> rolled GEMM -> rolled store.
// Block  8192  (64 threads): LU of W (log|det|) + writes logDet tail.
//
// Math: out[i,t,j] = sum_v phi[i,t,v] * W[(v+T0)%64, (j+T0)%64] + b[(j+T0)%64]
// Implemented as y[t,j'] = sum_u sphiT[(u-T0)%64][t] * W[u,j'] + b[j'],
// stored at j = (j' - T0) % 64.  (offs = (64-T0)&63; both rolls use +offs.)
// ---------------------------------------------------------------------------

union F2 { unsigned long long u; float2 f; };

__global__ void __launch_bounds__(64, 6) fused_kernel(
    const float* __restrict__ phi, const float* __restrict__ W,
    const float* __restrict__ b, float* __restrict__ out, int write_logdet)
{
    // ---------------- LU block ----------------
    if (blockIdx.x == NCONF) {
        __shared__ float A[64][65];
        __shared__ float m[64];
        __shared__ float rv[2];
        __shared__ int   ri[2];
        int tid = threadIdx.x;

        for (int idx = tid; idx < 64 * 64; idx += 64)
            A[idx >> 6][idx & 63] = W[idx];
        __syncthreads();

        float ld = 0.0f;
        for (int k = 0; k < 64; ++k) {
            float v  = (tid >= k) ? fabsf(A[tid][k]) : -1.0f;
            int   vi = tid;
            #pragma unroll
            for (int off = 16; off > 0; off >>= 1) {
                float ov = __shfl_down_sync(0xffffffffu, v,  off);
                int   oi = __shfl_down_sync(0xffffffffu, vi, off);
                if (ov > v) { v = ov; vi = oi; }
            }
            if ((tid & 31) == 0) { rv[tid >> 5] = v; ri[tid >> 5] = vi; }
            __syncthreads();
            int p = (rv[1] > rv[0]) ? ri[1] : ri[0];

            if (p != k) {
                float t1 = A[k][tid], t2 = A[p][tid];
                A[k][tid] = t2; A[p][tid] = t1;
            }
            __syncthreads();

            float piv = A[k][k];
            ld += logf(fabsf(piv));
            if (tid > k) m[tid] = A[tid][k] / piv;
            __syncthreads();

            if (tid > k) {
                float akj = A[k][tid];
                for (int r = k + 1; r < 64; ++r)
                    A[r][tid] -= m[r] * akj;
            }
            __syncthreads();
        }
        if (write_logdet) {
            float val = (float)NT * ld;
            float* tail = out + (size_t)NCONF * NT * NX;
            for (int idx = tid; idx < NCONF; idx += 64)
                tail[idx] = val;
        }
        return;
    }

    // ---------------- per-config GEMM block ----------------
    __shared__ float sphiT[64][68];  // [u][t], padded stride 68
    __shared__ float sW[64][64];     // W unrolled, [u][j']
    __shared__ float sb[64];
    __shared__ int   sT0;

    int i   = blockIdx.x;
    int tid = threadIdx.x;     // 64 threads
    int lane = tid & 31;

    // --- load phi tile (16KB) and transpose via 4x4 register blocks ---
    {
        const float4* g4 = reinterpret_cast<const float4*>(phi + (size_t)i * (NT * NX));
        int c  = tid & 15;        // u-block (x dimension, 4 floats)
        int a0 = tid >> 4;        // t-block base (0..3)
        #pragma unroll
        for (int it = 0; it < 4; ++it) {
            int a = a0 + 4 * it;  // t-block 0..15
            float4 r0 = g4[(4 * a + 0) * 16 + c];
            float4 r1 = g4[(4 * a + 1) * 16 + c];
            float4 r2 = g4[(4 * a + 2) * 16 + c];
            float4 r3 = g4[(4 * a + 3) * 16 + c];
            *reinterpret_cast<float4*>(&sphiT[4 * c + 0][4 * a]) = make_float4(r0.x, r1.x, r2.x, r3.x);
            *reinterpret_cast<float4*>(&sphiT[4 * c + 1][4 * a]) = make_float4(r0.y, r1.y, r2.y, r3.y);
            *reinterpret_cast<float4*>(&sphiT[4 * c + 2][4 * a]) = make_float4(r0.z, r1.z, r2.z, r3.z);
            *reinterpret_cast<float4*>(&sphiT[4 * c + 3][4 * a]) = make_float4(r0.w, r1.w, r2.w, r3.w);
        }
    }

    // --- load W (unrolled, coalesced float4, same 16KB for every CTA -> L2) ---
    {
        const float4* w4 = reinterpret_cast<const float4*>(W);
        float4* s4 = reinterpret_cast<float4*>(&sW[0][0]);
        #pragma unroll
        for (int k = 0; k < 16; ++k)
            s4[tid + 64 * k] = w4[tid + 64 * k];
    }
    sb[tid] = b[tid];
    __syncthreads();

    // --- T0 from sphiT rows 0 (x=0) and 1 (x=1): warp 0 only ---
    if (tid < 32) {
        float b0 = fabsf(sphiT[0][lane]);      int j0 = lane;
        float c0 = fabsf(sphiT[0][lane + 32]);
        if (c0 < b0) { b0 = c0; j0 = lane + 32; }
        float b1 = fabsf(sphiT[1][lane]);      int j1 = lane;
        float c1 = fabsf(sphiT[1][lane + 32]);
        if (c1 < b1) { b1 = c1; j1 = lane + 32; }
        #pragma unroll
        for (int off = 16; off > 0; off >>= 1) {
            float ob = __shfl_down_sync(0xffffffffu, b0, off);
            int   oj = __shfl_down_sync(0xffffffffu, j0, off);
            if (ob < b0 || (ob == b0 && oj < j0)) { b0 = ob; j0 = oj; }
            ob = __shfl_down_sync(0xffffffffu, b1, off);
            oj = __shfl_down_sync(0xffffffffu, j1, off);
            if (ob < b1 || (ob == b1 && oj < j1)) { b1 = ob; j1 = oj; }
        }
        if (lane == 0) sT0 = (j0 > j1) ? j1 : j0;
    }
    __syncthreads();

    int T0   = sT0;
    int offs = (64 - T0) & 63;

    // --- 8x8 per-thread tile GEMM with packed fma.rn.f32x2 ---
    int ty = tid >> 3;   // 0..7 : t-strip (8 rows)
    int tx = tid & 7;    // 0..7 : j'-strip (8 cols)
    const float* aBase = &sphiT[0][8 * ty];
    const float* wBase = &sW[0][8 * tx];

    unsigned long long acc[8][4];
    #pragma unroll
    for (int r = 0; r < 8; ++r)
        #pragma unroll
        for (int p = 0; p < 4; ++p) acc[r][p] = 0ull;

    #pragma unroll 8
    for (int u = 0; u < 64; ++u) {
        int row = (u + offs) & 63;
        const float* ap = aBase + row * 68;
        float4 a0 = *reinterpret_cast<const float4*>(ap);
        float4 a1 = *reinterpret_cast<const float4*>(ap + 4);
        ulonglong2 w0 = *reinterpret_cast<const ulonglong2*>(wBase + u * 64);
        ulonglong2 w1 = *reinterpret_cast<const ulonglong2*>(wBase + u * 64 + 4);

        unsigned long long ad[8];
        asm("mov.b64 %0, {%1, %1};" : "=l"(ad[0]) : "r"(__float_as_uint(a0.x)));
        asm("mov.b64 %0, {%1, %1};" : "=l"(ad[1]) : "r"(__float_as_uint(a0.y)));
        asm("mov.b64 %0, {%1, %1};" : "=l"(ad[2]) : "r"(__float_as_uint(a0.z)));
        asm("mov.b64 %0, {%1, %1};" : "=l"(ad[3]) : "r"(__float_as_uint(a0.w)));
        asm("mov.b64 %0, {%1, %1};" : "=l"(ad[4]) : "r"(__float_as_uint(a1.x)));
        asm("mov.b64 %0, {%1, %1};" : "=l"(ad[5]) : "r"(__float_as_uint(a1.y)));
        asm("mov.b64 %0, {%1, %1};" : "=l"(ad[6]) : "r"(__float_as_uint(a1.z)));
        asm("mov.b64 %0, {%1, %1};" : "=l"(ad[7]) : "r"(__float_as_uint(a1.w)));

        #pragma unroll
        for (int r = 0; r < 8; ++r) {
            asm("fma.rn.f32x2 %0, %1, %2, %0;" : "+l"(acc[r][0]) : "l"(ad[r]), "l"(w0.x));
            asm("fma.rn.f32x2 %0, %1, %2, %0;" : "+l"(acc[r][1]) : "l"(ad[r]), "l"(w0.y));
            asm("fma.rn.f32x2 %0, %1, %2, %0;" : "+l"(acc[r][2]) : "l"(ad[r]), "l"(w1.x));
            asm("fma.rn.f32x2 %0, %1, %2, %0;" : "+l"(acc[r][3]) : "l"(ad[r]), "l"(w1.y));
        }
    }

    // --- epilogue: +bias (j'-space), store rolled to j = (j' + offs) & 63 ---
    float bias[8];
    #pragma unroll
    for (int c = 0; c < 8; ++c) bias[c] = sb[8 * tx + c];

    float* obase = out + (size_t)i * (NT * NX);
    #pragma unroll
    for (int r = 0; r < 8; ++r) {
        float* orow = obase + (8 * ty + r) * NX;
        #pragma unroll
        for (int p = 0; p < 4; ++p) {
            F2 v; v.u = acc[r][p];
            int jp0 = 8 * tx + 2 * p;
            orow[(jp0 + offs) & 63]     = v.f.x + bias[2 * p];
            orow[(jp0 + 1 + offs) & 63] = v.f.y + bias[2 * p + 1];
        }
    }
}

// ---------------------------------------------------------------------------
extern "C" void kernel_launch(void* const* d_in, const int* in_sizes, int n_in,
                              void* d_out, int out_size) {
    const float* phi = nullptr;
    const float* W   = nullptr;
    const float* b   = nullptr;
    for (int k = 0; k < n_in; ++k) {
        if      (in_sizes[k] == NCONF * NT * NX) phi = (const float*)d_in[k];
        else if (in_sizes[k] == NX * NX)         W   = (const float*)d_in[k];
        else if (in_sizes[k] == NX)              b   = (const float*)d_in[k];
    }
    float* out = (float*)d_out;
    int write_logdet = (out_size >= NCONF * NT * NX + NCONF) ? 1 : 0;

    fused_kernel<<<NCONF + 1, 64>>>(phi, W, b, out, write_logdet);
}

// round 3
// speedup vs baseline: 1.3106x; 1.3106x over previous
#include <cuda_runtime.h>
#include <math.h>
#include <stdint.h>

#define NCONF 8192
#define NT 64
#define NX 64

// ---------------------------------------------------------------------------
// Fused kernel, grid = NCONF/2 + 1, 128 threads/CTA.
// Blocks 0..4095: two configs each. Block 4096: LU(W) + logDet tail.
//
// Math per config i:
//   out[i,t,j] = sum_v phi[i,t,v] * W[(v+T0)%64, (j+T0)%64] + b[(j+T0)%64]
// Rewritten (offs = (64-T0)&63):
//   y[t,j'] = sum_u phiT[(u+offs)%64][t] * W[u,j'] + b[j'],  out col j=(j'+offs)%64
// So W/b are used UNROLLED (shared by both configs; L2-resident),
// the roll lands on the A-row index (free ALU) and the store column.
//
// A is stored transposed in smem with a u-dependent swizzle:
//   sphiT[u][cfg*64 + (t + (u&60))&63] = phi[t][u]
// -> conflict-(near-)free transposed stores, conflict-free loop loads,
//    row stride exactly 128 floats (48KB total static smem).
// ---------------------------------------------------------------------------

union F2 { unsigned long long u; float2 f; };

__global__ void __launch_bounds__(128, 4) fused_kernel(
    const float* __restrict__ phi, const float* __restrict__ W,
    const float* __restrict__ b, float* __restrict__ out, int write_logdet)
{
    __shared__ float sphiT[64][128];   // 32 KB  [u][cfg*64 + swizzled t]
    __shared__ float sW[64][64];       // 16 KB  [u][j']

    int tid = threadIdx.x;

    // ---------------- LU block (reuses sphiT/sW storage) ----------------
    if (blockIdx.x == NCONF / 2) {
        float (*A)[65] = reinterpret_cast<float(*)[65]>(&sphiT[0][0]); // 16.6KB
        float* m  = &sW[0][0];
        float* rv = &sW[1][0];
        int*   ri = reinterpret_cast<int*>(&sW[1][4]);
        float* sld = &sW[1][8];

        for (int idx = tid; idx < 64 * 64; idx += 128)
            A[idx >> 6][idx & 63] = W[idx];
        __syncthreads();

        float ld = 0.0f;
        for (int k = 0; k < 64; ++k) {
            if (tid < 64) {
                float v  = (tid >= k) ? fabsf(A[tid][k]) : -1.0f;
                int   vi = tid;
                #pragma unroll
                for (int off = 16; off > 0; off >>= 1) {
                    float ov = __shfl_down_sync(0xffffffffu, v,  off);
                    int   oi = __shfl_down_sync(0xffffffffu, vi, off);
                    if (ov > v) { v = ov; vi = oi; }
                }
                if ((tid & 31) == 0) { rv[tid >> 5] = v; ri[tid >> 5] = vi; }
            }
            __syncthreads();
            int p = (rv[1] > rv[0]) ? ri[1] : ri[0];
            if (tid < 64 && p != k) {
                float t1 = A[k][tid], t2 = A[p][tid];
                A[k][tid] = t2; A[p][tid] = t1;
            }
            __syncthreads();
            float piv = A[k][k];
            if (tid < 64) {
                ld += logf(fabsf(piv));
                if (tid > k) m[tid] = A[tid][k] / piv;
            }
            __syncthreads();
            if (tid < 64 && tid > k) {
                float akj = A[k][tid];
                for (int r = k + 1; r < 64; ++r)
                    A[r][tid] -= m[r] * akj;
            }
            __syncthreads();
        }
        if (write_logdet) {
            if (tid == 0) *sld = ld;
            __syncthreads();
            float val = (float)NT * (*sld);
            float* tail = out + (size_t)NCONF * NT * NX;
            for (int idx = tid; idx < NCONF; idx += 128)
                tail[idx] = val;
        }
        return;
    }

    // ---------------- GEMM block: 2 configs ----------------
    int i0 = blockIdx.x * 2;

    // --- load phi for both configs, transpose via 4x4 register blocks ---
    {
        int half = tid >> 6;            // which config this thread loads
        int wtid = tid & 63;
        int cidx = wtid & 15;           // u-block
        int a0   = wtid >> 4;           // t-block base (0..3)
        int cbase = half * 64;
        const float4* g4 = reinterpret_cast<const float4*>(
            phi + (size_t)(i0 + half) * (NT * NX));
        #pragma unroll
        for (int it = 0; it < 4; ++it) {
            int a = a0 + 4 * it;        // t-block 0..15
            float4 r0 = g4[(4 * a + 0) * 16 + cidx];
            float4 r1 = g4[(4 * a + 1) * 16 + cidx];
            float4 r2 = g4[(4 * a + 2) * 16 + cidx];
            float4 r3 = g4[(4 * a + 3) * 16 + cidx];
            int col = (4 * a + 4 * cidx) & 63;   // swizzle: t' = (t + (u&60))&63
            *reinterpret_cast<float4*>(&sphiT[4 * cidx + 0][cbase + col]) =
                make_float4(r0.x, r1.x, r2.x, r3.x);
            *reinterpret_cast<float4*>(&sphiT[4 * cidx + 1][cbase + col]) =
                make_float4(r0.y, r1.y, r2.y, r3.y);
            *reinterpret_cast<float4*>(&sphiT[4 * cidx + 2][cbase + col]) =
                make_float4(r0.z, r1.z, r2.z, r3.z);
            *reinterpret_cast<float4*>(&sphiT[4 * cidx + 3][cbase + col]) =
                make_float4(r0.w, r1.w, r2.w, r3.w);
        }
    }

    // --- load W (coalesced float4; identical for all CTAs -> L2 hits) ---
    {
        const float4* w4 = reinterpret_cast<const float4*>(W);
        float4* s4 = reinterpret_cast<float4*>(&sW[0][0]);
        #pragma unroll
        for (int k = 0; k < 8; ++k)
            s4[tid + 128 * k] = w4[tid + 128 * k];
    }
    __syncthreads();

    // --- T0 for both configs, computed redundantly in every warp ---
    // u=0,1 rows have swizzle shift 0, so sphiT[x][cfg*64 + t] = phi[t][x].
    int lane = tid & 31;
    int T0c[2];
    #pragma unroll
    for (int c = 0; c < 2; ++c) {
        int cb = 64 * c;
        float b0 = fabsf(sphiT[0][cb + lane]);      int j0 = lane;
        float v0 = fabsf(sphiT[0][cb + lane + 32]);
        if (v0 < b0) { b0 = v0; j0 = lane + 32; }
        float b1 = fabsf(sphiT[1][cb + lane]);      int j1 = lane;
        float v1 = fabsf(sphiT[1][cb + lane + 32]);
        if (v1 < b1) { b1 = v1; j1 = lane + 32; }
        #pragma unroll
        for (int off = 16; off > 0; off >>= 1) {
            float ob = __shfl_down_sync(0xffffffffu, b0, off);
            int   oj = __shfl_down_sync(0xffffffffu, j0, off);
            if (ob < b0 || (ob == b0 && oj < j0)) { b0 = ob; j0 = oj; }
            ob = __shfl_down_sync(0xffffffffu, b1, off);
            oj = __shfl_down_sync(0xffffffffu, j1, off);
            if (ob < b1 || (ob == b1 && oj < j1)) { b1 = ob; j1 = oj; }
        }
        j0 = __shfl_sync(0xffffffffu, j0, 0);
        j1 = __shfl_sync(0xffffffffu, j1, 0);
        T0c[c] = (j0 > j1) ? j1 : j0;
    }

    int tx  = tid & 7;          // j'-strip: cols {4tx..4tx+3, 4tx+32..4tx+35}
    int ty  = tid >> 3;         // 0..15
    int tyc = ty & 7;           // t-strip within config: rows 8*tyc..+7
    int cfg = ty >> 3;          // warps 0-1 -> cfg0, warps 2-3 -> cfg1
    int offs = (64 - T0c[cfg]) & 63;
    int cbase2 = 64 * cfg;
    int tb = 8 * tyc;

    const float* wBase = &sW[0][0] + 4 * tx;

    unsigned long long acc[8][4];
    #pragma unroll
    for (int r = 0; r < 8; ++r)
        #pragma unroll
        for (int p = 0; p < 4; ++p) acc[r][p] = 0ull;

    #pragma unroll 8
    for (int u = 0; u < 64; ++u) {
        int row  = (u + offs) & 63;
        int colA = (tb + (row & 60)) & 63;
        const float* ap = &sphiT[row][cbase2];
        float4 a0 = *reinterpret_cast<const float4*>(ap + colA);
        float4 a1 = *reinterpret_cast<const float4*>(ap + ((colA + 4) & 63));
        ulonglong2 w0 = *reinterpret_cast<const ulonglong2*>(wBase + u * 64);
        ulonglong2 w1 = *reinterpret_cast<const ulonglong2*>(wBase + u * 64 + 32);

        unsigned long long ad[8];
        asm("mov.b64 %0, {%1, %1};" : "=l"(ad[0]) : "r"(__float_as_uint(a0.x)));
        asm("mov.b64 %0, {%1, %1};" : "=l"(ad[1]) : "r"(__float_as_uint(a0.y)));
        asm("mov.b64 %0, {%1, %1};" : "=l"(ad[2]) : "r"(__float_as_uint(a0.z)));
        asm("mov.b64 %0, {%1, %1};" : "=l"(ad[3]) : "r"(__float_as_uint(a0.w)));
        asm("mov.b64 %0, {%1, %1};" : "=l"(ad[4]) : "r"(__float_as_uint(a1.x)));
        asm("mov.b64 %0, {%1, %1};" : "=l"(ad[5]) : "r"(__float_as_uint(a1.y)));
        asm("mov.b64 %0, {%1, %1};" : "=l"(ad[6]) : "r"(__float_as_uint(a1.z)));
        asm("mov.b64 %0, {%1, %1};" : "=l"(ad[7]) : "r"(__float_as_uint(a1.w)));

        #pragma unroll
        for (int r = 0; r < 8; ++r) {
            asm("fma.rn.f32x2 %0, %1, %2, %0;" : "+l"(acc[r][0]) : "l"(ad[r]), "l"(w0.x));
            asm("fma.rn.f32x2 %0, %1, %2, %0;" : "+l"(acc[r][1]) : "l"(ad[r]), "l"(w0.y));
            asm("fma.rn.f32x2 %0, %1, %2, %0;" : "+l"(acc[r][2]) : "l"(ad[r]), "l"(w1.x));
            asm("fma.rn.f32x2 %0, %1, %2, %0;" : "+l"(acc[r][3]) : "l"(ad[r]), "l"(w1.y));
        }
    }

    // --- epilogue: +bias (j'-space), store rolled to j = (j'+offs)&63 ---
    float bias[8];
    #pragma unroll
    for (int c = 0; c < 4; ++c) {
        bias[c]     = b[4 * tx + c];
        bias[4 + c] = b[4 * tx + 32 + c];
    }

    float* obase = out + (size_t)(i0 + cfg) * (NT * NX) + tb * NX;
    #pragma unroll
    for (int r = 0; r < 8; ++r) {
        float* orow = obase + r * NX;
        #pragma unroll
        for (int p = 0; p < 4; ++p) {
            F2 v; v.u = acc[r][p];
            int jp = (p < 2) ? (4 * tx + 2 * p) : (4 * tx + 32 + 2 * (p - 2));
            orow[(jp + offs) & 63]     = v.f.x + bias[2 * p];
            orow[(jp + 1 + offs) & 63] = v.f.y + bias[2 * p + 1];
        }
    }
}

// ---------------------------------------------------------------------------
extern "C" void kernel_launch(void* const* d_in, const int* in_sizes, int n_in,
                              void* d_out, int out_size) {
    const float* phi = nullptr;
    const float* W   = nullptr;
    const float* b   = nullptr;
    for (int k = 0; k < n_in; ++k) {
        if      (in_sizes[k] == NCONF * NT * NX) phi = (const float*)d_in[k];
        else if (in_sizes[k] == NX * NX)         W   = (const float*)d_in[k];
        else if (in_sizes[k] == NX)              b   = (const float*)d_in[k];
    }
    float* out = (float*)d_out;
    int write_logdet = (out_size >= NCONF * NT * NX + NCONF) ? 1 : 0;

    fused_kernel<<<NCONF / 2 + 1, 128>>>(phi, W, b, out, write_logdet);
}